// round 13
// baseline (speedup 1.0000x reference)
#include <cuda_runtime.h>
#include <cuda_fp16.h>

#define N_NODES 100000
#define N_EDGES 1000000
#define D_FEAT 64
#define NBUCK ((N_NODES + 63) >> 6)     // 1563 buckets of 64 dst rows (8KB of fp16 rows each)
#define SCAN_T 256
#define SCAN_S 7                         // 256*7 = 1792 >= NBUCK
#define CONV_CHUNKS ((N_NODES * D_FEAT) / 8)

// Scratch (allocation-free rule: __device__ globals)
__device__ __half  g_hfeats[N_NODES * D_FEAT];  // 12.8 MB fp16 feature table
__device__ __half  g_exs[N_EDGES];              // ex in SORTED (bucket-grouped) order
__device__ float   g_sum[N_NODES];
__device__ int4    g_rec[N_EDGES];              // {src, dst, eid, 0} bucket-grouped
__device__ unsigned g_bins[NBUCK];              // zero-init; re-zeroed by div each call
__device__ unsigned g_off[NBUCK + 1];
__device__ unsigned g_cur[NBUCK];
__device__ unsigned g_conv_done = 0;            // convert block-completion counter (reset by div)
__device__ unsigned g_barcnt = 0;               // coop barrier (self-resetting)
__device__ unsigned g_bargen = 0;               // monotonic generation

__device__ __forceinline__ void grid_barrier() {
    __syncthreads();
    if (threadIdx.x == 0) {
        __threadfence();
        unsigned gen = atomicAdd(&g_bargen, 0u);
        __threadfence();
        if (atomicAdd(&g_barcnt, 1u) == gridDim.x - 1u) {
            g_barcnt = 0;
            __threadfence();
            atomicAdd(&g_bargen, 1u);
        } else {
            while (*(volatile unsigned*)&g_bargen == gen) { __nanosleep(64); }
        }
        __threadfence();
    }
    __syncthreads();
}

__device__ __forceinline__ unsigned pack_h2(float a, float b) {
    half2 h = __floats2half2_rn(a, b);
    return *reinterpret_cast<unsigned*>(&h);
}

__device__ __forceinline__ float dot8h(float4 a, float4 b) {
    const half2* pa = reinterpret_cast<const half2*>(&a);
    const half2* pb = reinterpret_cast<const half2*>(&b);
    float acc = 0.0f;
#pragma unroll
    for (int i = 0; i < 4; i++) {
        float2 fa = __half22float2(pa[i]);
        float2 fb = __half22float2(pb[i]);
        acc = fmaf(fa.x, fb.x, acc);
        acc = fmaf(fa.y, fb.y, acc);
    }
    return acc;
}

// ---------------------------------------------------------------------------
// K1 convert: fp32->fp16 table + zero g_sum. Grid-stride at 5 blocks/SM
// (leaves 3/SM of slots free so the independent hist/scan/scatter chain runs
// CONCURRENTLY). Early PDL trigger at start releases that chain immediately.
// Each block signals completion on g_conv_done; the edge kernel joins on it.
// ---------------------------------------------------------------------------
__global__ __launch_bounds__(256)
void convert_kernel(const float* __restrict__ feats) {
    cudaTriggerProgrammaticLaunchCompletion();

    const int gsize = gridDim.x * blockDim.x;
    const int gtid  = blockIdx.x * blockDim.x + threadIdx.x;

    for (int i = gtid; i < N_NODES; i += gsize) g_sum[i] = 0.0f;

    const float4* in4 = reinterpret_cast<const float4*>(feats);
    uint4* out4 = reinterpret_cast<uint4*>(g_hfeats);
    for (int i = gtid; i < CONV_CHUNKS; i += gsize) {
        float4 f0 = __ldg(in4 + i * 2 + 0);
        float4 f1 = __ldg(in4 + i * 2 + 1);
        uint4 packed;
        packed.x = pack_h2(f0.x, f0.y);
        packed.y = pack_h2(f0.z, f0.w);
        packed.z = pack_h2(f1.x, f1.y);
        packed.w = pack_h2(f1.z, f1.w);
        out4[i] = packed;
    }

    __syncthreads();
    if (threadIdx.x == 0) {
        __threadfence();                 // release hfeats/g_sum writes
        atomicAdd(&g_conv_done, 1u);
    }
}

// ---------------------------------------------------------------------------
// K2 histscan (cooperative, 256 blocks — fits the free slots next to convert):
// histogram dst buckets, grid barrier, block 0 exclusive-scans the 1563 bins
// into g_off / g_cur. Independent of convert; runs concurrent with it.
// g_bins pre-zeroed (static init on first call; div re-zeroes for replays).
// ---------------------------------------------------------------------------
__global__ __launch_bounds__(256)
void histscan_kernel(const int* __restrict__ dst) {
    const int gsize = gridDim.x * blockDim.x;
    const int gtid  = blockIdx.x * blockDim.x + threadIdx.x;

    const int4* d4 = reinterpret_cast<const int4*>(dst);
    for (int i = gtid; i < N_EDGES / 4; i += gsize) {
        int4 d = __ldg(d4 + i);
        atomicAdd(&g_bins[d.x >> 6], 1u);
        atomicAdd(&g_bins[d.y >> 6], 1u);
        atomicAdd(&g_bins[d.z >> 6], 1u);
        atomicAdd(&g_bins[d.w >> 6], 1u);
    }

    grid_barrier();

    if (blockIdx.x == 0) {
        __shared__ unsigned s_sums[SCAN_T];
        int t = threadIdx.x;
        unsigned local[SCAN_S];
        unsigned tot = 0;
#pragma unroll
        for (int j = 0; j < SCAN_S; j++) {
            int idx = t * SCAN_S + j;
            unsigned v = (idx < NBUCK) ? g_bins[idx] : 0u;
            local[j] = tot;              // prefix before element j
            tot += v;
        }
        s_sums[t] = tot;
        __syncthreads();
        for (int off = 1; off < SCAN_T; off <<= 1) {
            unsigned v = (t >= off) ? s_sums[t - off] : 0u;
            __syncthreads();
            s_sums[t] += v;
            __syncthreads();
        }
        unsigned base = s_sums[t] - tot; // exclusive prefix of this thread's span
#pragma unroll
        for (int j = 0; j < SCAN_S; j++) {
            int idx = t * SCAN_S + j;
            if (idx < NBUCK) {
                unsigned o = base + local[j];
                g_off[idx] = o;
                g_cur[idx] = o;
            }
        }
        if (t == SCAN_T - 1) g_off[NBUCK] = base + tot;   // == N_EDGES
    }
}

// ---------------------------------------------------------------------------
// K3 scatter: group edges by dst-bucket. pos via per-bucket cursor atomics
// (~640 ops/cursor, spread — cheap). Runs in leftover slots next to convert.
// ---------------------------------------------------------------------------
__global__ __launch_bounds__(256)
void scatter_kernel(const int* __restrict__ src,
                    const int* __restrict__ dst) {
    cudaGridDependencySynchronize();     // g_off/g_cur from histscan visible

    int i = blockIdx.x * blockDim.x + threadIdx.x;
    if (i >= N_EDGES) return;
    int s = __ldg(src + i);
    int d = __ldg(dst + i);
    unsigned p = atomicAdd(&g_cur[d >> 6], 1u);
    g_rec[p] = make_int4(s, d, i, 0);
}

// ---------------------------------------------------------------------------
// K4 edge: one block per bucket. The bucket's 64 dst rows (8KB) stay
// L1-resident -> dst gather L2 traffic collapses 128MB -> ~13MB. src rows
// stream with evict-first hint. Joins on convert via g_conv_done flag
// (records visibility via PDL sync on scatter).
// ex = exp(exp(-0.01|dot|)); segment-max skipped exactly (shift-invariance,
// e in (0.6,1]); ex rounded to fp16, the same value feeds the atomic sum.
// ---------------------------------------------------------------------------
__global__ __launch_bounds__(256)
void edge_kernel(int conv_grid) {
    cudaGridDependencySynchronize();     // scatter's g_rec visible

    if (threadIdx.x == 0) {
        while (*(volatile unsigned*)&g_conv_done < (unsigned)conv_grid)
            __nanosleep(128);
        __threadfence();                 // acquire hfeats/g_sum
    }
    __syncthreads();

    unsigned start = g_off[blockIdx.x];
    unsigned end   = g_off[blockIdx.x + 1];
    const int sub  = threadIdx.x & 3;
    const int quad = threadIdx.x >> 2;   // 0..63

    for (unsigned base = start; base < end; base += 64) {
        unsigned pos  = base + quad;
        bool valid    = pos < end;
        unsigned posc = valid ? pos : end - 1;   // clamp: keep all lanes in shfl

        int4 rec = g_rec[posc];

        const float4* fs = reinterpret_cast<const float4*>(g_hfeats + (size_t)rec.x * D_FEAT);
        const float4* fd = reinterpret_cast<const float4*>(g_hfeats + (size_t)rec.y * D_FEAT);

        float4 a0 = __ldcs(fs + sub);            // src: stream, no reuse
        float4 a1 = __ldcs(fs + sub + 4);
        float4 b0 = fd[sub];                     // dst: default cache (L1 reuse)
        float4 b1 = fd[sub + 4];

        float acc = dot8h(a0, b0) + dot8h(a1, b1);
        acc += __shfl_down_sync(0xFFFFFFFFu, acc, 2);
        acc += __shfl_down_sync(0xFFFFFFFFu, acc, 1);

        if (sub == 0 && valid) {
            float e  = __expf(-0.01f * fabsf(acc));   // in (0.6, 1]
            float ex = __expf(e);                     // in (1.9, 2.8)
            __half h = __float2half_rn(ex);
            g_exs[pos] = h;
            atomicAdd(&g_sum[rec.y], __half2float(h));
        }
    }
}

// ---------------------------------------------------------------------------
// K5 div: sorted order — records contiguous, sums L1-resident per bucket run,
// output scattered to original edge order (merges in L2). Also resets
// per-call state (bins, conv counter) for the next graph replay.
// ---------------------------------------------------------------------------
__global__ __launch_bounds__(256)
void div_kernel(float* __restrict__ out) {
    cudaGridDependencySynchronize();     // edge's g_exs/g_sum visible

    int i = blockIdx.x * blockDim.x + threadIdx.x;
    if (i < NBUCK) g_bins[i] = 0u;
    if (i == 0)    g_conv_done = 0u;
    if (i >= N_EDGES) return;

    int4 rec = g_rec[i];
    float v = __half2float(g_exs[i]) / g_sum[rec.y];
    out[rec.z] = v;
}

// ---------------------------------------------------------------------------
static void launch_pdl(void* func, dim3 grid, dim3 block, void** args) {
    cudaLaunchConfig_t cfg = {};
    cfg.gridDim = grid;
    cfg.blockDim = block;
    cfg.dynamicSmemBytes = 0;
    cfg.stream = 0;
    cudaLaunchAttribute attr[1];
    attr[0].id = cudaLaunchAttributeProgrammaticStreamSerialization;
    attr[0].val.programmaticStreamSerializationAllowed = 1;
    cfg.attrs = attr;
    cfg.numAttrs = 1;
    cudaLaunchKernelExC(&cfg, func, args);
}

extern "C" void kernel_launch(void* const* d_in, const int* in_sizes, int n_in,
                              void* d_out, int out_size) {
    const float* feats = (const float*)d_in[0];
    const int*   src   = (const int*)d_in[1];
    const int*   dst   = (const int*)d_in[2];
    float* out = (float*)d_out;

    int dev = 0, sms = 0;
    cudaGetDevice(&dev);
    cudaDeviceGetAttribute(&sms, cudaDevAttrMultiProcessorCount, dev);
    int conv_grid = sms * 5;             // leave ~3 blocks/SM free for the sort chain

    // convert (plain launch, early trigger) — releases the concurrent chain
    convert_kernel<<<conv_grid, 256>>>(feats);

    {   // histscan: concurrent with convert (no grid-dep sync inside)
        void* args[1] = { (void*)&dst };
        launch_pdl((void*)histscan_kernel, dim3(256), dim3(256), args);
    }
    {   // scatter: after histscan completes; overlaps convert's remainder
        void* args[2] = { (void*)&src, (void*)&dst };
        launch_pdl((void*)scatter_kernel,
                   dim3((N_EDGES + 255) / 256), dim3(256), args);
    }
    {   // edge: after scatter; flag-join on convert
        void* args[1] = { (void*)&conv_grid };
        launch_pdl((void*)edge_kernel, dim3(NBUCK), dim3(256), args);
    }
    {   // div: after edge
        void* args[1] = { (void*)&out };
        launch_pdl((void*)div_kernel,
                   dim3((N_EDGES + 255) / 256), dim3(256), args);
    }
}

// round 15
// speedup vs baseline: 2.8877x; 2.8877x over previous
#include <cuda_runtime.h>
#include <cuda_fp16.h>

#define N_NODES 100000
#define N_EDGES 1000000
#define D_FEAT 64
#define E32 128000                       // edges handled in fp32 during the convert window
#define CONV_CHUNKS ((N_NODES * D_FEAT) / 8)

// Scratch (allocation-free rule: __device__ globals)
__device__ __half  g_hfeats[N_NODES * D_FEAT];  // 12.8 MB fp16 feature table
__device__ __half  g_exh[N_EDGES];              // 2 MB per-edge ex (fp16)
__device__ float   g_sum[N_NODES];              // static zero-init; re-zeroed by zero_kernel
__device__ unsigned g_conv_done = 0;            // convert block-completion counter

__device__ __forceinline__ unsigned pack_h2(float a, float b) {
    half2 h = __floats2half2_rn(a, b);
    return *reinterpret_cast<unsigned*>(&h);
}

__device__ __forceinline__ float dot8h(float4 a, float4 b) {
    const half2* pa = reinterpret_cast<const half2*>(&a);
    const half2* pb = reinterpret_cast<const half2*>(&b);
    float acc = 0.0f;
#pragma unroll
    for (int i = 0; i < 4; i++) {
        float2 fa = __half22float2(pa[i]);
        float2 fb = __half22float2(pb[i]);
        acc = fmaf(fa.x, fb.x, acc);
        acc = fmaf(fa.y, fb.y, acc);
    }
    return acc;
}

// Shared epilogue: e = exp(-0.01|dot|) in (0.6,1] -> no segment-max needed
// (softmax shift-invariance, skipped exactly). ex rounded to fp16; the SAME
// rounded value feeds the atomic sum so rounding largely cancels in the ratio.
__device__ __forceinline__ void emit_edge(int eid, int d, float acc) {
    float e  = __expf(-0.01f * fabsf(acc));
    float ex = __expf(e);
    __half h = __float2half_rn(ex);
    g_exh[eid] = h;
    atomicAdd(&g_sum[d], __half2float(h));
}

// ---------------------------------------------------------------------------
// K1 convert: fp32->fp16 table ONLY. Grid-stride at 5 blocks/SM — fully
// resident when launched first, leaving 3/SM of slots for concurrent edge32.
// Early PDL trigger releases edge32's launch at kernel start. Each block
// signals completion on g_conv_done; edge16 flag-joins on it (robust even if
// the scheduler or profiler serializes the kernels).
// ---------------------------------------------------------------------------
__global__ __launch_bounds__(256)
void convert_kernel(const float* __restrict__ feats) {
    cudaTriggerProgrammaticLaunchCompletion();

    const int gsize = gridDim.x * blockDim.x;
    const int gtid  = blockIdx.x * blockDim.x + threadIdx.x;

    const float4* in4 = reinterpret_cast<const float4*>(feats);
    uint4* out4 = reinterpret_cast<uint4*>(g_hfeats);
    for (int i = gtid; i < CONV_CHUNKS; i += gsize) {
        float4 f0 = __ldg(in4 + i * 2 + 0);
        float4 f1 = __ldg(in4 + i * 2 + 1);
        uint4 packed;
        packed.x = pack_h2(f0.x, f0.y);
        packed.y = pack_h2(f0.z, f0.w);
        packed.z = pack_h2(f1.x, f1.y);
        packed.w = pack_h2(f1.z, f1.w);
        out4[i] = packed;
    }

    __syncthreads();
    if (threadIdx.x == 0) {
        __threadfence();                 // release hfeats writes
        atomicAdd(&g_conv_done, 1u);
    }
}

// ---------------------------------------------------------------------------
// K2 edge32 (PDL secondary, NO dependency sync — independent of convert):
// edges [0, E32) against the ORIGINAL fp32 feats. Runs concurrently with
// convert in the free slots, reading the same bytes convert streams (L2
// dedups). 8 lanes/edge; 256B fp32 row = 16 float4; lane takes sub, sub+8.
// g_sum pre-zeroed by the previous replay's zero_kernel (static zero-init on
// the very first call).
// ---------------------------------------------------------------------------
__global__ __launch_bounds__(256)
void edge32_kernel(const float* __restrict__ feats,
                   const int* __restrict__ src,
                   const int* __restrict__ dst) {
    cudaTriggerProgrammaticLaunchCompletion();   // release edge16's launch

    int tid = blockIdx.x * blockDim.x + threadIdx.x;
    int eid = tid >> 3;
    int sub = tid & 7;
    if (eid >= E32) return;

    int s = __ldg(src + eid);
    int d = __ldg(dst + eid);

    const float4* fs = reinterpret_cast<const float4*>(feats + (size_t)s * D_FEAT);
    const float4* fd = reinterpret_cast<const float4*>(feats + (size_t)d * D_FEAT);

    float4 a0 = fs[sub];
    float4 a1 = fs[sub + 8];
    float4 b0 = fd[sub];
    float4 b1 = fd[sub + 8];

    float acc = a0.x * b0.x + a0.y * b0.y + a0.z * b0.z + a0.w * b0.w
              + a1.x * b1.x + a1.y * b1.y + a1.z * b1.z + a1.w * b1.w;

    acc += __shfl_down_sync(0xFFFFFFFFu, acc, 4);
    acc += __shfl_down_sync(0xFFFFFFFFu, acc, 2);
    acc += __shfl_down_sync(0xFFFFFFFFu, acc, 1);

    if (sub == 0) emit_edge(eid, d, acc);
}

// ---------------------------------------------------------------------------
// K3 edge16 (PDL secondary): edges [E32, N_EDGES) against the fp16 table.
// Prefetches indices, then flag-joins on convert completion.
// 4 lanes/edge; 128B fp16 row covered by 4 contiguous LDG.128.
// ---------------------------------------------------------------------------
__global__ __launch_bounds__(256)
void edge16_kernel(const int* __restrict__ src,
                   const int* __restrict__ dst,
                   int conv_grid) {
    int tid = blockIdx.x * blockDim.x + threadIdx.x;
    int eid = E32 + (tid >> 2);
    int sub = tid & 3;
    if (eid >= N_EDGES) return;

    // Independent prefetch (runs while convert still streams)
    int s = __ldg(src + eid);
    int d = __ldg(dst + eid);

    if (threadIdx.x == 0) {
        while (atomicAdd(&g_conv_done, 0u) < (unsigned)conv_grid)
            __nanosleep(128);
        __threadfence();                 // acquire hfeats
    }
    __syncthreads();

    const float4* fs = reinterpret_cast<const float4*>(g_hfeats + (size_t)s * D_FEAT);
    const float4* fd = reinterpret_cast<const float4*>(g_hfeats + (size_t)d * D_FEAT);

    float4 a0 = fs[sub];
    float4 a1 = fs[sub + 4];
    float4 b0 = fd[sub];
    float4 b1 = fd[sub + 4];

    float acc = dot8h(a0, b0) + dot8h(a1, b1);

    acc += __shfl_down_sync(0xFFFFFFFFu, acc, 2);
    acc += __shfl_down_sync(0xFFFFFFFFu, acc, 1);

    if (sub == 0) emit_edge(eid, d, acc);
}

// ---------------------------------------------------------------------------
// K4 div (PDL secondary): prefetch dst pair, dependency-sync (edge16 done;
// edge32 complete by stream order), then divide. 2 edges/thread.
// ---------------------------------------------------------------------------
__global__ __launch_bounds__(256)
void div_kernel(const int* __restrict__ dst,
                float* __restrict__ out) {
    int i = blockIdx.x * blockDim.x + threadIdx.x;        // pair index
    if (i >= N_EDGES / 2) return;

    int2 d2 = __ldg(reinterpret_cast<const int2*>(dst) + i);

    cudaGridDependencySynchronize();

    half2 eh = reinterpret_cast<const half2*>(g_exh)[i];
    float s0 = g_sum[d2.x];
    float s1 = g_sum[d2.y];
    float2 ef = __half22float2(eh);

    float2 o;
    o.x = ef.x / s0;
    o.y = ef.y / s1;
    __stcs(reinterpret_cast<float2*>(out) + i, o);
}

// ---------------------------------------------------------------------------
// K5 zero: reset g_sum + convert flag for the NEXT replay (after div has
// consumed the sums). First call covered by static zero-init.
// ---------------------------------------------------------------------------
__global__ __launch_bounds__(256)
void zero_kernel() {
    cudaGridDependencySynchronize();     // div must finish reading g_sum
    int i = blockIdx.x * blockDim.x + threadIdx.x;
    if (i < N_NODES) g_sum[i] = 0.0f;
    if (i == 0)      g_conv_done = 0u;
}

// ---------------------------------------------------------------------------
static void launch_pdl(const void* func, dim3 grid, dim3 block, void** args) {
    cudaLaunchConfig_t cfg = {};
    cfg.gridDim = grid;
    cfg.blockDim = block;
    cfg.dynamicSmemBytes = 0;
    cfg.stream = 0;
    cudaLaunchAttribute attr[1];
    attr[0].id = cudaLaunchAttributeProgrammaticStreamSerialization;
    attr[0].val.programmaticStreamSerializationAllowed = 1;
    cfg.attrs = attr;
    cfg.numAttrs = 1;
    cudaLaunchKernelExC(&cfg, func, args);
}

extern "C" void kernel_launch(void* const* d_in, const int* in_sizes, int n_in,
                              void* d_out, int out_size) {
    const float* feats = (const float*)d_in[0];
    const int*   src   = (const int*)d_in[1];
    const int*   dst   = (const int*)d_in[2];
    float* out = (float*)d_out;

    int dev = 0, sms = 0;
    cudaGetDevice(&dev);
    cudaDeviceGetAttribute(&sms, cudaDevAttrMultiProcessorCount, dev);
    int conv_grid = sms * 5;             // 5/SM resident; ~3/SM left for edge32

    convert_kernel<<<conv_grid, 256>>>(feats);

    {   // fp32 edges, concurrent with convert
        void* args[3] = { (void*)&feats, (void*)&src, (void*)&dst };
        launch_pdl((const void*)edge32_kernel,
                   dim3((E32 * 8) / 256), dim3(256), args);
    }
    {   // fp16 edges, flag-joined on convert
        void* args[3] = { (void*)&src, (void*)&dst, (void*)&conv_grid };
        launch_pdl((const void*)edge16_kernel,
                   dim3(((N_EDGES - E32) * 4 + 255) / 256), dim3(256), args);
    }
    {
        void* args[2] = { (void*)&dst, (void*)&out };
        launch_pdl((const void*)div_kernel,
                   dim3(((N_EDGES / 2) + 255) / 256), dim3(256), args);
    }
    launch_pdl((const void*)zero_kernel,
               dim3((N_NODES + 255) / 256), dim3(256), nullptr);
}

// round 16
// speedup vs baseline: 4.1736x; 1.4453x over previous
#include <cuda_runtime.h>
#include <cuda_fp16.h>

#define N_NODES 100000
#define N_EDGES 1000000
#define D_FEAT 64

// Scratch (allocation-free rule: __device__ globals)
__device__ __half g_hfeats[N_NODES * D_FEAT];   // 12.8 MB fp16 feature table
__device__ __half g_exh[N_EDGES];               // 2 MB per-edge ex (fp16)
__device__ float  g_sum[N_NODES];

__device__ __forceinline__ unsigned pack_h2(float a, float b) {
    half2 h = __floats2half2_rn(a, b);
    return *reinterpret_cast<unsigned*>(&h);
}

__device__ __forceinline__ float dot8h(float4 a, float4 b) {
    const half2* pa = reinterpret_cast<const half2*>(&a);
    const half2* pb = reinterpret_cast<const half2*>(&b);
    float acc = 0.0f;
#pragma unroll
    for (int i = 0; i < 4; i++) {
        float2 fa = __half22float2(pa[i]);
        float2 fb = __half22float2(pb[i]);
        acc = fmaf(fa.x, fb.x, acc);
        acc = fmaf(fa.y, fb.y, acc);
    }
    return acc;
}

// ---------------------------------------------------------------------------
// Kernel 1: fp32->fp16 convert (8 elems/thread, 800k threads) + zero g_sum
// (replaces a separate memset node). Measured at its mixed-R/W DRAM ceiling.
// ---------------------------------------------------------------------------
__global__ __launch_bounds__(256)
void convert_kernel(const float* __restrict__ feats) {
    int i = blockIdx.x * blockDim.x + threadIdx.x;        // 8-elem index
    if (i < N_NODES) g_sum[i] = 0.0f;
    if (i >= (N_NODES * D_FEAT) / 8) return;

    const float4* in = reinterpret_cast<const float4*>(feats) + i * 2;
    float4 f0 = __ldg(in);
    float4 f1 = __ldg(in + 1);

    uint4 packed;
    packed.x = pack_h2(f0.x, f0.y);
    packed.y = pack_h2(f0.z, f0.w);
    packed.z = pack_h2(f1.x, f1.y);
    packed.w = pack_h2(f1.z, f1.w);
    reinterpret_cast<uint4*>(g_hfeats)[i] = packed;
}

// ---------------------------------------------------------------------------
// Kernel 2 (PDL secondary): prefetch src/dst indices BEFORE the grid
// dependency sync (overlaps the 8MB index read + launch ramp with convert's
// tail), then gather fp16 rows, dot, ex = exp(exp(-0.01|dot|)), atomicAdd.
// 4 lanes/edge; 128B fp16 row covered by 4 contiguous LDG.128 — this phase
// runs at the L2 gather roofline (256MB of row traffic).
// Segment-max pass skipped exactly (softmax shift-invariance; e in (0.6,1]
// needs no stabilization). ex rounded to fp16; the SAME rounded value feeds
// the sum, so rounding largely cancels in the final ratio.
// ---------------------------------------------------------------------------
__global__ __launch_bounds__(256)
void edge_kernel(const int* __restrict__ src,
                 const int* __restrict__ dst) {
    int tid = blockIdx.x * blockDim.x + threadIdx.x;
    int eid = tid >> 2;      // 4 lanes per edge
    int sub = tid & 3;
    if (eid >= N_EDGES) return;

    // Independent of convert's output — issue before the dependency sync.
    int s = __ldg(src + eid);
    int d = __ldg(dst + eid);

    cudaGridDependencySynchronize();   // wait for convert's writes to be visible

    const float4* fs = reinterpret_cast<const float4*>(g_hfeats + (size_t)s * D_FEAT);
    const float4* fd = reinterpret_cast<const float4*>(g_hfeats + (size_t)d * D_FEAT);

    float4 a0 = fs[sub];
    float4 a1 = fs[sub + 4];
    float4 b0 = fd[sub];
    float4 b1 = fd[sub + 4];

    float acc = dot8h(a0, b0) + dot8h(a1, b1);

    acc += __shfl_down_sync(0xFFFFFFFFu, acc, 2);
    acc += __shfl_down_sync(0xFFFFFFFFu, acc, 1);

    if (sub == 0) {
        float e  = __expf(-0.01f * fabsf(acc));   // in (0.6, 1]
        float ex = __expf(e);                     // in (1.9, 2.8)
        __half h = __float2half_rn(ex);
        g_exh[eid] = h;
        atomicAdd(&g_sum[d], __half2float(h));
    }
}

// ---------------------------------------------------------------------------
// Kernel 3 (PDL secondary): prefetch dst pair before the sync, then
// out[e] = ex[e] / sum[dst[e]], 2 edges/thread (500k threads of latency
// hiding for the random g_sum gather). Output store is streaming
// (write-once, never re-read).
// ---------------------------------------------------------------------------
__global__ __launch_bounds__(256)
void div_kernel(const int* __restrict__ dst,
                float* __restrict__ out) {
    int i = blockIdx.x * blockDim.x + threadIdx.x;        // pair index
    if (i >= N_EDGES / 2) return;

    // Independent of edge's output — issue before the dependency sync.
    int2 d2 = __ldg(reinterpret_cast<const int2*>(dst) + i);

    cudaGridDependencySynchronize();   // wait for edge's g_exh / g_sum

    half2 eh = reinterpret_cast<const half2*>(g_exh)[i];
    float s0 = g_sum[d2.x];
    float s1 = g_sum[d2.y];
    float2 ef = __half22float2(eh);

    float2 o;
    o.x = ef.x / s0;
    o.y = ef.y / s1;
    __stcs(reinterpret_cast<float2*>(out) + i, o);
}

// ---------------------------------------------------------------------------
static void launch_pdl(void* func, dim3 grid, dim3 block, void** args) {
    cudaLaunchConfig_t cfg = {};
    cfg.gridDim = grid;
    cfg.blockDim = block;
    cfg.dynamicSmemBytes = 0;
    cfg.stream = 0;
    cudaLaunchAttribute attr[1];
    attr[0].id = cudaLaunchAttributeProgrammaticStreamSerialization;
    attr[0].val.programmaticStreamSerializationAllowed = 1;
    cfg.attrs = attr;
    cfg.numAttrs = 1;
    cudaLaunchKernelExC(&cfg, func, args);
}

extern "C" void kernel_launch(void* const* d_in, const int* in_sizes, int n_in,
                              void* d_out, int out_size) {
    const float* feats = (const float*)d_in[0];
    const int*   src   = (const int*)d_in[1];
    const int*   dst   = (const int*)d_in[2];
    float* out = (float*)d_out;

    convert_kernel<<<((N_NODES * D_FEAT / 8) + 255) / 256, 256>>>(feats);

    {
        void* args[2] = { (void*)&src, (void*)&dst };
        launch_pdl((void*)edge_kernel,
                   dim3((N_EDGES * 4 + 255) / 256), dim3(256), args);
    }
    {
        void* args[2] = { (void*)&dst, (void*)&out };
        launch_pdl((void*)div_kernel,
                   dim3(((N_EDGES / 2) + 255) / 256), dim3(256), args);
    }
}

// round 17
// speedup vs baseline: 4.3511x; 1.0425x over previous
#include <cuda_runtime.h>
#include <cuda_fp16.h>

#define N_NODES 100000
#define N_EDGES 1000000
#define EHALF (N_EDGES / 2)
#define D_FEAT 64

// Scratch (allocation-free rule: __device__ globals)
__device__ __half g_hfeats[N_NODES * D_FEAT];   // 12.8 MB fp16 feature table
__device__ __half g_exh[N_EDGES];               // 2 MB per-edge ex (fp16)
__device__ float  g_sum[N_NODES];

__device__ __forceinline__ unsigned pack_h2(float a, float b) {
    half2 h = __floats2half2_rn(a, b);
    return *reinterpret_cast<unsigned*>(&h);
}

__device__ __forceinline__ float dot8h(float4 a, float4 b) {
    const half2* pa = reinterpret_cast<const half2*>(&a);
    const half2* pb = reinterpret_cast<const half2*>(&b);
    float acc = 0.0f;
#pragma unroll
    for (int i = 0; i < 4; i++) {
        float2 fa = __half22float2(pa[i]);
        float2 fb = __half22float2(pb[i]);
        acc = fmaf(fa.x, fb.x, acc);
        acc = fmaf(fa.y, fb.y, acc);
    }
    return acc;
}

// e = exp(-0.01|dot|) in (0.6,1] -> segment-max skipped exactly (softmax
// shift-invariance). ex rounded to fp16; the SAME rounded value feeds the
// atomic sum so rounding largely cancels in the final ratio.
__device__ __forceinline__ void emit_edge(int eid, int d, float acc) {
    float e  = __expf(-0.01f * fabsf(acc));
    float ex = __expf(e);
    __half h = __float2half_rn(ex);
    g_exh[eid] = h;
    atomicAdd(&g_sum[d], __half2float(h));
}

// ---------------------------------------------------------------------------
// Kernel 1: fp32->fp16 convert (8 elems/thread, 800k threads) + zero g_sum.
// Measured at its mixed-R/W DRAM ceiling — unchanged from champion.
// ---------------------------------------------------------------------------
__global__ __launch_bounds__(256)
void convert_kernel(const float* __restrict__ feats) {
    int i = blockIdx.x * blockDim.x + threadIdx.x;        // 8-elem index
    if (i < N_NODES) g_sum[i] = 0.0f;
    if (i >= (N_NODES * D_FEAT) / 8) return;

    const float4* in = reinterpret_cast<const float4*>(feats) + i * 2;
    float4 f0 = __ldg(in);
    float4 f1 = __ldg(in + 1);

    uint4 packed;
    packed.x = pack_h2(f0.x, f0.y);
    packed.y = pack_h2(f0.z, f0.w);
    packed.z = pack_h2(f1.x, f1.y);
    packed.w = pack_h2(f1.z, f1.w);
    reinterpret_cast<uint4*>(g_hfeats)[i] = packed;
}

// ---------------------------------------------------------------------------
// Kernel 2 (PDL secondary): TWO edges per thread-quad (eid and eid+EHALF) —
// 8 independent gather LDG.128 in flight per thread (double the MLP of the
// champion) to test whether the edge phase has latency slack below the L2
// throughput cap. Index prefetch before the dependency sync as before.
// ---------------------------------------------------------------------------
__global__ __launch_bounds__(256)
void edge_kernel(const int* __restrict__ src,
                 const int* __restrict__ dst) {
    int tid  = blockIdx.x * blockDim.x + threadIdx.x;
    int eid0 = tid >> 2;     // first edge of the pair
    int sub  = tid & 3;
    if (eid0 >= EHALF) return;
    int eid1 = eid0 + EHALF;

    // Independent of convert's output — issue before the dependency sync.
    int s0 = __ldg(src + eid0);
    int d0 = __ldg(dst + eid0);
    int s1 = __ldg(src + eid1);
    int d1 = __ldg(dst + eid1);

    cudaGridDependencySynchronize();   // convert's writes visible

    const float4* fs0 = reinterpret_cast<const float4*>(g_hfeats + (size_t)s0 * D_FEAT);
    const float4* fd0 = reinterpret_cast<const float4*>(g_hfeats + (size_t)d0 * D_FEAT);
    const float4* fs1 = reinterpret_cast<const float4*>(g_hfeats + (size_t)s1 * D_FEAT);
    const float4* fd1 = reinterpret_cast<const float4*>(g_hfeats + (size_t)d1 * D_FEAT);

    // 8 independent 16B loads — all issued before first use.
    float4 a0 = fs0[sub];
    float4 a1 = fs0[sub + 4];
    float4 b0 = fd0[sub];
    float4 b1 = fd0[sub + 4];
    float4 c0 = fs1[sub];
    float4 c1 = fs1[sub + 4];
    float4 e0 = fd1[sub];
    float4 e1 = fd1[sub + 4];

    float acc0 = dot8h(a0, b0) + dot8h(a1, b1);
    float acc1 = dot8h(c0, e0) + dot8h(c1, e1);

    acc0 += __shfl_down_sync(0xFFFFFFFFu, acc0, 2);
    acc0 += __shfl_down_sync(0xFFFFFFFFu, acc0, 1);
    acc1 += __shfl_down_sync(0xFFFFFFFFu, acc1, 2);
    acc1 += __shfl_down_sync(0xFFFFFFFFu, acc1, 1);

    if (sub == 0) {
        emit_edge(eid0, d0, acc0);
        emit_edge(eid1, d1, acc1);
    }
}

// ---------------------------------------------------------------------------
// Kernel 3 (PDL secondary): prefetch dst pair before the sync, then
// out[e] = ex[e] / sum[dst[e]], 2 edges/thread — unchanged from champion.
// ---------------------------------------------------------------------------
__global__ __launch_bounds__(256)
void div_kernel(const int* __restrict__ dst,
                float* __restrict__ out) {
    int i = blockIdx.x * blockDim.x + threadIdx.x;        // pair index
    if (i >= N_EDGES / 2) return;

    int2 d2 = __ldg(reinterpret_cast<const int2*>(dst) + i);

    cudaGridDependencySynchronize();   // edge's g_exh / g_sum visible

    half2 eh = reinterpret_cast<const half2*>(g_exh)[i];
    float s0 = g_sum[d2.x];
    float s1 = g_sum[d2.y];
    float2 ef = __half22float2(eh);

    float2 o;
    o.x = ef.x / s0;
    o.y = ef.y / s1;
    __stcs(reinterpret_cast<float2*>(out) + i, o);
}

// ---------------------------------------------------------------------------
static void launch_pdl(void* func, dim3 grid, dim3 block, void** args) {
    cudaLaunchConfig_t cfg = {};
    cfg.gridDim = grid;
    cfg.blockDim = block;
    cfg.dynamicSmemBytes = 0;
    cfg.stream = 0;
    cudaLaunchAttribute attr[1];
    attr[0].id = cudaLaunchAttributeProgrammaticStreamSerialization;
    attr[0].val.programmaticStreamSerializationAllowed = 1;
    cfg.attrs = attr;
    cfg.numAttrs = 1;
    cudaLaunchKernelExC(&cfg, func, args);
}

extern "C" void kernel_launch(void* const* d_in, const int* in_sizes, int n_in,
                              void* d_out, int out_size) {
    const float* feats = (const float*)d_in[0];
    const int*   src   = (const int*)d_in[1];
    const int*   dst   = (const int*)d_in[2];
    float* out = (float*)d_out;

    convert_kernel<<<((N_NODES * D_FEAT / 8) + 255) / 256, 256>>>(feats);

    {
        void* args[2] = { (void*)&src, (void*)&dst };
        launch_pdl((void*)edge_kernel,
                   dim3((EHALF * 4 + 255) / 256), dim3(256), args);
    }
    {
        void* args[2] = { (void*)&dst, (void*)&out };
        launch_pdl((void*)div_kernel,
                   dim3(((N_EDGES / 2) + 255) / 256), dim3(256), args);
    }
}